// round 10
// baseline (speedup 1.0000x reference)
#include <cuda_runtime.h>
#include <math.h>
#include <stdint.h>

// MoE router: tf32 mma.sync (3-term split) + exact fp64 recheck for near-ties.
// BM=64, 2 CTAs/SM for latency hiding.
// x: [16384, 2048] f32, W: [2048, 64] f32
// out (f32): dispatch[16384*64], probs[16384*64], tkp[16384*2], tki[16384*2]

#define M_TOK   16384
#define K_DIM   2048
#define N_EXP   64
#define BM      64
#define BK      32
#define NT      (K_DIM / BK)          // 64
#define THREADS 256
#define GAP_TH  2e-3f

// stride 36 -> bank = (4g+qi) mod 32: conflict-free frag loads.
#define XH_OFF       0                // 64 x 36
#define XL_OFF       2304
#define WH_OFF       4608             // 64 x 36 (W^T: [n][k])
#define WL_OFF       6912
#define STAGE_FLOATS 9216
#define SMEM_BYTES   (2 * STAGE_FLOATS * 4)   // 73728 B

#define OFF_DISP  0
#define OFF_PROBS (M_TOK * N_EXP)
#define OFF_TKP   (2 * M_TOK * N_EXP)
#define OFF_TKI   (2 * M_TOK * N_EXP + 2 * M_TOK)

__device__ __forceinline__ unsigned f2tf32(float f) {
    unsigned u;
    asm("cvt.rna.tf32.f32 %0, %1;" : "=r"(u) : "f"(f));
    return u;
}

__device__ __forceinline__ void mma_tf32(float* c, const unsigned* a, const unsigned* b) {
    asm volatile(
        "mma.sync.aligned.m16n8k8.row.col.f32.tf32.tf32.f32 "
        "{%0,%1,%2,%3}, {%4,%5,%6,%7}, {%8,%9}, {%0,%1,%2,%3};"
        : "+f"(c[0]), "+f"(c[1]), "+f"(c[2]), "+f"(c[3])
        : "r"(a[0]), "r"(a[1]), "r"(a[2]), "r"(a[3]), "r"(b[0]), "r"(b[1]));
}

__global__ __launch_bounds__(THREADS, 2)
void moe_mma_kernel(const float* __restrict__ x,
                    const float* __restrict__ W,
                    float* __restrict__ out) {
    extern __shared__ float sm[];
    __shared__ float s_max[BM], s_inv[BM];
    __shared__ int   s_i1[BM], s_i2[BM], s_i3[BM];
    __shared__ int   s_nflag;
    __shared__ int   s_flist[BM];

    const int t    = threadIdx.x;
    const int wid  = t >> 5;
    const int lane = t & 31;
    const int g    = lane >> 2;       // 0..7
    const int qi   = lane & 3;        // 0..3
    const int tok0 = blockIdx.x * BM;
    const int m0   = (wid & 3) * 16;  // warp's 16-row slice
    const int n0   = (wid >> 2) * 4;  // warp's n-tile base (4 tiles of 8)

    // x: 64 rows x 32 k per tile; thread -> row t>>2, 8 floats at (t&3)*8
    const int xrow = t >> 2;
    const int xq   = t & 3;
    const float* xg = x + (size_t)(tok0 + xrow) * K_DIM + xq * 8;
    // W: 32 k x 64 experts; thread -> expert t&63, 8 k's at (t>>6)*8
    const int wn  = t & 63;
    const int wkq = t >> 6;
    const float* wg = W + (size_t)(wkq * 8) * N_EXP + wn;

    if (t == 0) s_nflag = 0;

    float4 xb[2];
    float  wb[8];
#pragma unroll
    for (int j = 0; j < 2; j++) xb[j] = *reinterpret_cast<const float4*>(xg + j * 4);
#pragma unroll
    for (int j = 0; j < 8; j++) wb[j] = wg[(size_t)j * N_EXP];

    float acc[4][4];                  // 4 n-tiles x 4 C regs
#pragma unroll
    for (int n = 0; n < 4; n++)
#pragma unroll
        for (int c = 0; c < 4; c++) acc[n][c] = 0.f;

#pragma unroll 1
    for (int kt = 0; kt < NT; kt++) {
        const int s = kt & 1;
        unsigned* sth = reinterpret_cast<unsigned*>(sm + s * STAGE_FLOATS);

        // ---- convert prefetched tile -> tf32 hi/lo, store (uint4 STS) ----
        {
            uint4 h[2], l[2];
#pragma unroll
            for (int j = 0; j < 2; j++) {
                float4 v = xb[j];
                h[j].x = f2tf32(v.x); h[j].y = f2tf32(v.y);
                h[j].z = f2tf32(v.z); h[j].w = f2tf32(v.w);
                l[j].x = f2tf32(v.x - __uint_as_float(h[j].x));
                l[j].y = f2tf32(v.y - __uint_as_float(h[j].y));
                l[j].z = f2tf32(v.z - __uint_as_float(h[j].z));
                l[j].w = f2tf32(v.w - __uint_as_float(h[j].w));
            }
            int o = xrow * 36 + xq * 8;
#pragma unroll
            for (int j = 0; j < 2; j++) {
                *reinterpret_cast<uint4*>(sth + XH_OFF + o + j * 4) = h[j];
                *reinterpret_cast<uint4*>(sth + XL_OFF + o + j * 4) = l[j];
            }
        }
        {
            unsigned hh[8], ll[8];
#pragma unroll
            for (int j = 0; j < 8; j++) {
                hh[j] = f2tf32(wb[j]);
                ll[j] = f2tf32(wb[j] - __uint_as_float(hh[j]));
            }
            int o = wn * 36 + wkq * 8;
            uint4 h0 = {hh[0], hh[1], hh[2], hh[3]}, h1 = {hh[4], hh[5], hh[6], hh[7]};
            uint4 l0 = {ll[0], ll[1], ll[2], ll[3]}, l1 = {ll[4], ll[5], ll[6], ll[7]};
            *reinterpret_cast<uint4*>(sth + WH_OFF + o)     = h0;
            *reinterpret_cast<uint4*>(sth + WH_OFF + o + 4) = h1;
            *reinterpret_cast<uint4*>(sth + WL_OFF + o)     = l0;
            *reinterpret_cast<uint4*>(sth + WL_OFF + o + 4) = l1;
        }
        __syncthreads();

        // ---- prefetch tile kt+1 into regs (overlaps compute) ----
        if (kt + 1 < NT) {
            const float* xgn = xg + (kt + 1) * BK;
#pragma unroll
            for (int j = 0; j < 2; j++) xb[j] = *reinterpret_cast<const float4*>(xgn + j * 4);
            const float* wgn = wg + (size_t)(kt + 1) * BK * N_EXP;
#pragma unroll
            for (int j = 0; j < 8; j++) wb[j] = wgn[(size_t)j * N_EXP];
        }

        // ---- compute: 4 k8 steps x 4 n-tiles x 3 terms ----
        const unsigned* xh = sth + XH_OFF;
        const unsigned* xl = sth + XL_OFF;
        const unsigned* wh = sth + WH_OFF;
        const unsigned* wl = sth + WL_OFF;
        const int offa  = (m0 + g) * 36 + qi;
        const int offb0 = g * 36 + qi;
#pragma unroll
        for (int ks = 0; ks < 4; ks++) {
            const int oa = offa + ks * 8;
            unsigned ah[4], al[4];
            ah[0] = xh[oa];     ah[1] = xh[oa + 8 * 36];
            ah[2] = xh[oa + 4]; ah[3] = xh[oa + 8 * 36 + 4];
            al[0] = xl[oa];     al[1] = xl[oa + 8 * 36];
            al[2] = xl[oa + 4]; al[3] = xl[oa + 8 * 36 + 4];
#pragma unroll
            for (int nt = 0; nt < 4; nt++) {
                const int ob = offb0 + (n0 + nt) * 8 * 36 + ks * 8;
                unsigned bh[2] = { wh[ob], wh[ob + 4] };
                unsigned bl[2] = { wl[ob], wl[ob + 4] };
                mma_tf32(acc[nt], ah, bh);
                mma_tf32(acc[nt], al, bh);
                mma_tf32(acc[nt], ah, bl);
            }
        }
    }
    __syncthreads();

    // ---- dump logits to smem [64][65] ----
    float* lg = sm;
#pragma unroll
    for (int nt = 0; nt < 4; nt++) {
        int c0 = (n0 + nt) * 8 + qi * 2;
        lg[(m0 + g) * 65 + c0]         = acc[nt][0];
        lg[(m0 + g) * 65 + c0 + 1]     = acc[nt][1];
        lg[(m0 + g + 8) * 65 + c0]     = acc[nt][2];
        lg[(m0 + g + 8) * 65 + c0 + 1] = acc[nt][3];
    }
    __syncthreads();

    // ---- phase 1: per-token top-3 + softmax denom; flag near-ties ----
    if (t < BM) {
        const float* row = lg + t * 65;
        float b1 = -INFINITY, b2 = -INFINITY, b3 = -INFINITY;
        int i1 = 0, i2 = 0, i3 = 0;
#pragma unroll
        for (int e = 0; e < N_EXP; e++) {
            float v = row[e];
            if (v > b1)      { b3 = b2; i3 = i2; b2 = b1; i2 = i1; b1 = v; i1 = e; }
            else if (v > b2) { b3 = b2; i3 = i2; b2 = v;  i2 = e; }
            else if (v > b3) { b3 = v;  i3 = e; }
        }
        float ssum = 0.f;
#pragma unroll
        for (int e = 0; e < N_EXP; e++) ssum += __expf(row[e] - b1);
        s_max[t] = b1;
        s_inv[t] = 1.f / ssum;
        s_i1[t] = i1; s_i2[t] = i2; s_i3[t] = i3;
        if ((b1 - b2 < GAP_TH) || (b2 - b3 < GAP_TH)) {
            int slot = atomicAdd(&s_nflag, 1);
            s_flist[slot] = t;
        }
    }
    __syncthreads();

    // ---- recheck: one warp per flagged token, exact fp64 top-3 ----
    const int nflag = s_nflag;
    for (int f = wid; f < nflag; f += 8) {
        const int tok = s_flist[f];
        const int e0 = s_i1[tok], e1 = s_i2[tok], e2 = s_i3[tok];
        const float* xr = x + (size_t)(tok0 + tok) * K_DIM;
        double d0 = 0.0, d1 = 0.0, d2 = 0.0;
        for (int k = lane; k < K_DIM; k += 32) {
            double xv = (double)xr[k];
            const float* wrow = W + (size_t)k * N_EXP;
            d0 = fma(xv, (double)wrow[e0], d0);
            d1 = fma(xv, (double)wrow[e1], d1);
            d2 = fma(xv, (double)wrow[e2], d2);
        }
#pragma unroll
        for (int off = 16; off > 0; off >>= 1) {
            d0 += __shfl_xor_sync(0xffffffff, d0, off);
            d1 += __shfl_xor_sync(0xffffffff, d1, off);
            d2 += __shfl_xor_sync(0xffffffff, d2, off);
        }
        if (lane == 0) {
            double v[3] = { d0, d1, d2 };
            int    ix[3] = { e0, e1, e2 };
#pragma unroll
            for (int a = 0; a < 2; a++)
#pragma unroll
                for (int b = 0; b < 2 - a; b++) {
                    bool sw = (v[b] < v[b + 1]) ||
                              (v[b] == v[b + 1] && ix[b] > ix[b + 1]);
                    if (sw) {
                        double tv = v[b]; v[b] = v[b + 1]; v[b + 1] = tv;
                        int ti = ix[b]; ix[b] = ix[b + 1]; ix[b + 1] = ti;
                    }
                }
            s_i1[tok] = ix[0];
            s_i2[tok] = ix[1];
        }
    }
    __syncthreads();

    // ---- phase 1b: tkp/tki from (possibly corrected) indices ----
    if (t < BM) {
        const float* row = lg + t * 65;
        int i1 = s_i1[t], i2 = s_i2[t];
        float b1 = s_max[t], inv = s_inv[t];
        int gtok = tok0 + t;
        out[OFF_TKP + gtok * 2 + 0] = __expf(row[i1] - b1) * inv;
        out[OFF_TKP + gtok * 2 + 1] = __expf(row[i2] - b1) * inv;
        out[OFF_TKI + gtok * 2 + 0] = (float)i1;
        out[OFF_TKI + gtok * 2 + 1] = (float)i2;
    }
    __syncthreads();

    // ---- phase 2: coalesced probs + dispatch ----
#pragma unroll
    for (int idx = t; idx < BM * N_EXP; idx += THREADS) {
        int tok = idx >> 6;
        int e   = idx & 63;
        float p = __expf(lg[tok * 65 + e] - s_max[tok]) * s_inv[tok];
        int gtok = tok0 + tok;
        out[OFF_PROBS + (size_t)gtok * N_EXP + e] = p;
        out[OFF_DISP  + (size_t)gtok * N_EXP + e] =
            (e == s_i1[tok] || e == s_i2[tok]) ? 1.f : 0.f;
    }
}

extern "C" void kernel_launch(void* const* d_in, const int* in_sizes, int n_in,
                              void* d_out, int out_size) {
    const float* x = (const float*)d_in[0];
    const float* W = (const float*)d_in[1];
    float* out = (float*)d_out;

    static bool attr_set = false;
    if (!attr_set) {
        cudaFuncSetAttribute(moe_mma_kernel,
                             cudaFuncAttributeMaxDynamicSharedMemorySize, SMEM_BYTES);
        attr_set = true;
    }
    moe_mma_kernel<<<M_TOK / BM, THREADS, SMEM_BYTES>>>(x, W, out);
}

// round 11
// speedup vs baseline: 1.0189x; 1.0189x over previous
#include <cuda_runtime.h>
#include <math.h>
#include <stdint.h>

// MoE router: tf32 mma.sync (3-term split) + exact fp64 recheck for near-ties.
// BM=128, BK=64, 512 threads, 1 CTA/SM (4 warps/SMSP), grid 128.
// x: [16384, 2048] f32, W: [2048, 64] f32
// out (f32): dispatch[16384*64], probs[16384*64], tkp[16384*2], tki[16384*2]

#define M_TOK   16384
#define K_DIM   2048
#define N_EXP   64
#define BM      128
#define BK      64
#define NT      (K_DIM / BK)          // 32
#define THREADS 512
#define GAP_TH  2e-3f

// stride 68 (64 k + 4 pad): bank = (4*row + col) mod 32 -> conflict-free frags
#define XSTR         68
#define XH_OFF       0                // 128 x 68
#define XL_OFF       8704
#define WH_OFF       17408            // 64 x 68 (W^T: [n][k])
#define WL_OFF       21760
#define STAGE_FLOATS 26112
#define SMEM_BYTES   (2 * STAGE_FLOATS * 4)   // 208896 B

#define OFF_DISP  0
#define OFF_PROBS (M_TOK * N_EXP)
#define OFF_TKP   (2 * M_TOK * N_EXP)
#define OFF_TKI   (2 * M_TOK * N_EXP + 2 * M_TOK)

__device__ __forceinline__ unsigned f2tf32(float f) {
    unsigned u;
    asm("cvt.rna.tf32.f32 %0, %1;" : "=r"(u) : "f"(f));
    return u;
}

__device__ __forceinline__ void mma_tf32(float* c, const unsigned* a, const unsigned* b) {
    asm volatile(
        "mma.sync.aligned.m16n8k8.row.col.f32.tf32.tf32.f32 "
        "{%0,%1,%2,%3}, {%4,%5,%6,%7}, {%8,%9}, {%0,%1,%2,%3};"
        : "+f"(c[0]), "+f"(c[1]), "+f"(c[2]), "+f"(c[3])
        : "r"(a[0]), "r"(a[1]), "r"(a[2]), "r"(a[3]), "r"(b[0]), "r"(b[1]));
}

__global__ __launch_bounds__(THREADS, 1)
void moe_mma_kernel(const float* __restrict__ x,
                    const float* __restrict__ W,
                    float* __restrict__ out) {
    extern __shared__ float sm[];
    __shared__ float s_max[BM], s_inv[BM];
    __shared__ int   s_i1[BM], s_i2[BM], s_i3[BM];
    __shared__ int   s_nflag;
    __shared__ int   s_flist[BM];

    const int t    = threadIdx.x;
    const int wid  = t >> 5;          // 0..15
    const int lane = t & 31;
    const int g    = lane >> 2;       // 0..7
    const int qi   = lane & 3;        // 0..3
    const int tok0 = blockIdx.x * BM;
    const int m0   = (wid & 7) * 16;  // warp's 16-row slice
    const int n0   = (wid >> 3) * 4;  // warp's 4 n-tiles (of 8)

    // x: 128 rows x 64 k per tile; 2048 uint4 / 512 thr = 4 chunks each
    int xr[4], xc[4];
#pragma unroll
    for (int r = 0; r < 4; r++) {
        int idx = t + r * THREADS;
        xr[r] = idx >> 4;             // 0..127
        xc[r] = idx & 15;             // uint4 within 64-k row
    }
    // W: 64 k x 64 experts; thread -> expert t&63, 8 k's at (t>>6)*8
    const int wn  = t & 63;
    const int wkq = t >> 6;           // 0..7
    const float* wg0 = W + (size_t)(wkq * 8) * N_EXP + wn;

    if (t == 0) s_nflag = 0;

    float4 xb[4];
    float  wb[8];
#pragma unroll
    for (int r = 0; r < 4; r++)
        xb[r] = *reinterpret_cast<const float4*>(
            x + (size_t)(tok0 + xr[r]) * K_DIM + xc[r] * 4);
#pragma unroll
    for (int j = 0; j < 8; j++) wb[j] = wg0[(size_t)j * N_EXP];

    float acc[4][4];                  // 4 n-tiles x 4 C regs
#pragma unroll
    for (int n = 0; n < 4; n++)
#pragma unroll
        for (int c = 0; c < 4; c++) acc[n][c] = 0.f;

#pragma unroll 1
    for (int kt = 0; kt < NT; kt++) {
        const int s = kt & 1;
        unsigned* sth = reinterpret_cast<unsigned*>(sm + s * STAGE_FLOATS);

        // ---- convert prefetched tile -> tf32 hi/lo, store (uint4 STS) ----
#pragma unroll
        for (int r = 0; r < 4; r++) {
            float4 v = xb[r];
            uint4 h, l;
            h.x = f2tf32(v.x); h.y = f2tf32(v.y); h.z = f2tf32(v.z); h.w = f2tf32(v.w);
            l.x = f2tf32(v.x - __uint_as_float(h.x));
            l.y = f2tf32(v.y - __uint_as_float(h.y));
            l.z = f2tf32(v.z - __uint_as_float(h.z));
            l.w = f2tf32(v.w - __uint_as_float(h.w));
            int o = xr[r] * XSTR + xc[r] * 4;
            *reinterpret_cast<uint4*>(sth + XH_OFF + o) = h;
            *reinterpret_cast<uint4*>(sth + XL_OFF + o) = l;
        }
        {
            unsigned hh[8], ll[8];
#pragma unroll
            for (int j = 0; j < 8; j++) {
                hh[j] = f2tf32(wb[j]);
                ll[j] = f2tf32(wb[j] - __uint_as_float(hh[j]));
            }
            int o = wn * XSTR + wkq * 8;
            uint4 h0 = {hh[0], hh[1], hh[2], hh[3]}, h1 = {hh[4], hh[5], hh[6], hh[7]};
            uint4 l0 = {ll[0], ll[1], ll[2], ll[3]}, l1 = {ll[4], ll[5], ll[6], ll[7]};
            *reinterpret_cast<uint4*>(sth + WH_OFF + o)     = h0;
            *reinterpret_cast<uint4*>(sth + WH_OFF + o + 4) = h1;
            *reinterpret_cast<uint4*>(sth + WL_OFF + o)     = l0;
            *reinterpret_cast<uint4*>(sth + WL_OFF + o + 4) = l1;
        }
        __syncthreads();

        // ---- prefetch tile kt+1 into regs (overlaps compute) ----
        if (kt + 1 < NT) {
            const int kb = (kt + 1) * BK;
#pragma unroll
            for (int r = 0; r < 4; r++)
                xb[r] = *reinterpret_cast<const float4*>(
                    x + (size_t)(tok0 + xr[r]) * K_DIM + kb + xc[r] * 4);
            const float* wgn = wg0 + (size_t)kb * N_EXP;
#pragma unroll
            for (int j = 0; j < 8; j++) wb[j] = wgn[(size_t)j * N_EXP];
        }

        // ---- compute: 8 k8 steps x 4 n-tiles x 3 terms ----
        const unsigned* xh = sth + XH_OFF;
        const unsigned* xl = sth + XL_OFF;
        const unsigned* wh = sth + WH_OFF;
        const unsigned* wl = sth + WL_OFF;
        const int offa  = (m0 + g) * XSTR + qi;
        const int offb0 = g * XSTR + qi;
#pragma unroll
        for (int ks = 0; ks < 8; ks++) {
            const int oa = offa + ks * 8;
            unsigned ah[4], al[4];
            ah[0] = xh[oa];     ah[1] = xh[oa + 8 * XSTR];
            ah[2] = xh[oa + 4]; ah[3] = xh[oa + 8 * XSTR + 4];
            al[0] = xl[oa];     al[1] = xl[oa + 8 * XSTR];
            al[2] = xl[oa + 4]; al[3] = xl[oa + 8 * XSTR + 4];
#pragma unroll
            for (int nt = 0; nt < 4; nt++) {
                const int ob = offb0 + (n0 + nt) * 8 * XSTR + ks * 8;
                unsigned bh[2] = { wh[ob], wh[ob + 4] };
                unsigned bl[2] = { wl[ob], wl[ob + 4] };
                mma_tf32(acc[nt], ah, bh);
                mma_tf32(acc[nt], al, bh);
                mma_tf32(acc[nt], ah, bl);
            }
        }
    }
    __syncthreads();

    // ---- dump logits to smem [128][65] ----
    float* lg = sm;
#pragma unroll
    for (int nt = 0; nt < 4; nt++) {
        int c0 = (n0 + nt) * 8 + qi * 2;
        lg[(m0 + g) * 65 + c0]         = acc[nt][0];
        lg[(m0 + g) * 65 + c0 + 1]     = acc[nt][1];
        lg[(m0 + g + 8) * 65 + c0]     = acc[nt][2];
        lg[(m0 + g + 8) * 65 + c0 + 1] = acc[nt][3];
    }
    __syncthreads();

    // ---- phase 1: per-token top-3 + softmax denom; flag near-ties ----
    if (t < BM) {
        const float* row = lg + t * 65;
        float b1 = -INFINITY, b2 = -INFINITY, b3 = -INFINITY;
        int i1 = 0, i2 = 0, i3 = 0;
#pragma unroll
        for (int e = 0; e < N_EXP; e++) {
            float v = row[e];
            if (v > b1)      { b3 = b2; i3 = i2; b2 = b1; i2 = i1; b1 = v; i1 = e; }
            else if (v > b2) { b3 = b2; i3 = i2; b2 = v;  i2 = e; }
            else if (v > b3) { b3 = v;  i3 = e; }
        }
        float ssum = 0.f;
#pragma unroll
        for (int e = 0; e < N_EXP; e++) ssum += __expf(row[e] - b1);
        s_max[t] = b1;
        s_inv[t] = 1.f / ssum;
        s_i1[t] = i1; s_i2[t] = i2; s_i3[t] = i3;
        if ((b1 - b2 < GAP_TH) || (b2 - b3 < GAP_TH)) {
            int slot = atomicAdd(&s_nflag, 1);
            s_flist[slot] = t;
        }
    }
    __syncthreads();

    // ---- recheck: one warp per flagged token, exact fp64 top-3 ----
    const int nflag = s_nflag;
    for (int f = wid; f < nflag; f += 16) {
        const int tok = s_flist[f];
        const int e0 = s_i1[tok], e1 = s_i2[tok], e2 = s_i3[tok];
        const float* xrow = x + (size_t)(tok0 + tok) * K_DIM;
        double d0 = 0.0, d1 = 0.0, d2 = 0.0;
        for (int k = lane; k < K_DIM; k += 32) {
            double xv = (double)xrow[k];
            const float* wrow = W + (size_t)k * N_EXP;
            d0 = fma(xv, (double)wrow[e0], d0);
            d1 = fma(xv, (double)wrow[e1], d1);
            d2 = fma(xv, (double)wrow[e2], d2);
        }
#pragma unroll
        for (int off = 16; off > 0; off >>= 1) {
            d0 += __shfl_xor_sync(0xffffffff, d0, off);
            d1 += __shfl_xor_sync(0xffffffff, d1, off);
            d2 += __shfl_xor_sync(0xffffffff, d2, off);
        }
        if (lane == 0) {
            double v[3] = { d0, d1, d2 };
            int    ix[3] = { e0, e1, e2 };
#pragma unroll
            for (int a = 0; a < 2; a++)
#pragma unroll
                for (int b = 0; b < 2 - a; b++) {
                    bool sw = (v[b] < v[b + 1]) ||
                              (v[b] == v[b + 1] && ix[b] > ix[b + 1]);
                    if (sw) {
                        double tv = v[b]; v[b] = v[b + 1]; v[b + 1] = tv;
                        int ti = ix[b]; ix[b] = ix[b + 1]; ix[b + 1] = ti;
                    }
                }
            s_i1[tok] = ix[0];
            s_i2[tok] = ix[1];
        }
    }
    __syncthreads();

    // ---- phase 1b: tkp/tki from (possibly corrected) indices ----
    if (t < BM) {
        const float* row = lg + t * 65;
        int i1 = s_i1[t], i2 = s_i2[t];
        float b1 = s_max[t], inv = s_inv[t];
        int gtok = tok0 + t;
        out[OFF_TKP + gtok * 2 + 0] = __expf(row[i1] - b1) * inv;
        out[OFF_TKP + gtok * 2 + 1] = __expf(row[i2] - b1) * inv;
        out[OFF_TKI + gtok * 2 + 0] = (float)i1;
        out[OFF_TKI + gtok * 2 + 1] = (float)i2;
    }
    __syncthreads();

    // ---- phase 2: coalesced probs + dispatch ----
#pragma unroll
    for (int idx = t; idx < BM * N_EXP; idx += THREADS) {
        int tok = idx >> 6;
        int e   = idx & 63;
        float p = __expf(lg[tok * 65 + e] - s_max[tok]) * s_inv[tok];
        int gtok = tok0 + tok;
        out[OFF_PROBS + (size_t)gtok * N_EXP + e] = p;
        out[OFF_DISP  + (size_t)gtok * N_EXP + e] =
            (e == s_i1[tok] || e == s_i2[tok]) ? 1.f : 0.f;
    }
}

extern "C" void kernel_launch(void* const* d_in, const int* in_sizes, int n_in,
                              void* d_out, int out_size) {
    const float* x = (const float*)d_in[0];
    const float* W = (const float*)d_in[1];
    float* out = (float*)d_out;

    static bool attr_set = false;
    if (!attr_set) {
        cudaFuncSetAttribute(moe_mma_kernel,
                             cudaFuncAttributeMaxDynamicSharedMemorySize, SMEM_BYTES);
        attr_set = true;
    }
    moe_mma_kernel<<<M_TOK / BM, THREADS, SMEM_BYTES>>>(x, W, out);
}

// round 12
// speedup vs baseline: 1.4175x; 1.3912x over previous
#include <cuda_runtime.h>
#include <math.h>

// MoE router, fp32 f32x2 SIMT, broadcast-W design (crossbar-light).
// warp = 32 tokens (lane=token) x 16 experts; W frag loads are LDS broadcasts.
// BM=128, 512 threads, full K per CTA, grid 128. Fused softmax/top2 epilogue.
// x: [16384, 2048] f32, W: [2048, 64] f32
// out (f32): dispatch[16384*64], probs[16384*64], tkp[16384*2], tki[16384*2]

#define M_TOK   16384
#define K_DIM   2048
#define N_EXP   64
#define BM      128
#define BK      32
#define NT      (K_DIM / BK)          // 64
#define THREADS 512

// stage layout (floats): xs [128 tok][36] (32k + 4 pad, rows 144B aligned),
// then ws [32 k][64]
#define XS_STRIDE    36
#define WS_OFF       (BM * XS_STRIDE)         // 4608
#define STAGE_FLOATS (WS_OFF + BK * N_EXP)    // 6656
#define SMEM_BYTES   (2 * STAGE_FLOATS * 4)   // 53248 B

#define OFF_DISP  0
#define OFF_PROBS (M_TOK * N_EXP)
#define OFF_TKP   (2 * M_TOK * N_EXP)
#define OFF_TKI   (2 * M_TOK * N_EXP + 2 * M_TOK)

__device__ __forceinline__ unsigned long long pack2(float v) {
    unsigned long long r;
    asm("mov.b64 %0, {%1, %1};" : "=l"(r) : "f"(v));
    return r;
}
__device__ __forceinline__ void unpack2(unsigned long long v, float& lo, float& hi) {
    asm("mov.b64 {%0, %1}, %2;" : "=f"(lo), "=f"(hi) : "l"(v));
}
__device__ __forceinline__ void ffma2(unsigned long long& c, unsigned long long a,
                                      unsigned long long b) {
    asm("fma.rn.f32x2 %0, %1, %2, %0;" : "+l"(c) : "l"(a), "l"(b));
}
__device__ __forceinline__ void cp16(unsigned dst, const void* src) {
    asm volatile("cp.async.cg.shared.global [%0], [%1], 16;\n" :: "r"(dst), "l"(src));
}
#define CP_COMMIT() asm volatile("cp.async.commit_group;\n" ::: "memory")
#define CP_WAIT0()  asm volatile("cp.async.wait_group 0;\n" ::: "memory")

__global__ __launch_bounds__(THREADS, 1)
void moe_router_kernel(const float* __restrict__ x,
                       const float* __restrict__ W,
                       float* __restrict__ out) {
    extern __shared__ float sm[];
    __shared__ float s_max[BM], s_inv[BM];
    __shared__ int   s_i1[BM], s_i2[BM];

    const int t    = threadIdx.x;
    const int wid  = t >> 5;
    const int lane = t & 31;
    const int tokl = (wid & 3) * 32 + lane;   // this thread's token (0..127)
    const int e0   = (wid >> 2) * 16;         // this thread's 16 experts
    const int tok0 = blockIdx.x * BM;
    const unsigned smb = (unsigned)__cvta_generic_to_shared(sm);

    // cp.async mappings
    // x: 128 tok x 32 k = 1024 x 16B chunks; 2 per thread
    const int xt0 = t >> 2,           xc0 = t & 3;           // wait: need idx>>3
    // (recompute properly below)
    // W: 32 k x 64 e = 512 x 16B chunks; 1 per thread
    const int wk = t >> 4, wc = t & 15;

    // x chunk assignments: idx = t, t+512 -> tok = idx>>3 (0..127), c8 = idx&7
    const int xa_tok[2] = { t >> 3, (t + 512) >> 3 };
    const int xa_c8 [2] = { t & 7,  (t + 512) & 7 };

    unsigned long long acc[8];        // 16 experts as 8 f32x2
#pragma unroll
    for (int p = 0; p < 8; p++) acc[p] = 0ull;

    // ---- prologue: stage 0 ----
#pragma unroll
    for (int r = 0; r < 2; r++)
        cp16(smb + (unsigned)(xa_tok[r] * XS_STRIDE + xa_c8[r] * 4) * 4,
             x + (size_t)(tok0 + xa_tok[r]) * K_DIM + xa_c8[r] * 4);
    cp16(smb + (unsigned)(WS_OFF + wk * N_EXP + wc * 4) * 4,
         W + (size_t)wk * N_EXP + wc * 4);
    CP_COMMIT();

#pragma unroll 1
    for (int kt = 0; kt < NT; kt++) {
        const int s = kt & 1;
        CP_WAIT0();
        __syncthreads();

        // prefetch tile kt+1 into the other stage (race-free: after barrier)
        if (kt + 1 < NT) {
            const int sn = s ^ 1;
            const int kb = (kt + 1) * BK;
            const unsigned sb = smb + (unsigned)(sn * STAGE_FLOATS) * 4;
#pragma unroll
            for (int r = 0; r < 2; r++)
                cp16(sb + (unsigned)(xa_tok[r] * XS_STRIDE + xa_c8[r] * 4) * 4,
                     x + (size_t)(tok0 + xa_tok[r]) * K_DIM + kb + xa_c8[r] * 4);
            cp16(sb + (unsigned)(WS_OFF + wk * N_EXP + wc * 4) * 4,
                 W + (size_t)(kb + wk) * N_EXP + wc * 4);
            CP_COMMIT();
        }

        // ---- compute on stage s ----
        const float* xsp = sm + s * STAGE_FLOATS + tokl * XS_STRIDE;
        const float* wsp = sm + s * STAGE_FLOATS + WS_OFF + e0;

#pragma unroll
        for (int k4 = 0; k4 < BK / 4; k4++) {
            float4 xv = *reinterpret_cast<const float4*>(xsp + k4 * 4);
#pragma unroll
            for (int kk = 0; kk < 4; kk++) {
                const float* wrow = wsp + (k4 * 4 + kk) * N_EXP;
                ulonglong2 w01 = *reinterpret_cast<const ulonglong2*>(wrow);
                ulonglong2 w23 = *reinterpret_cast<const ulonglong2*>(wrow + 4);
                ulonglong2 w45 = *reinterpret_cast<const ulonglong2*>(wrow + 8);
                ulonglong2 w67 = *reinterpret_cast<const ulonglong2*>(wrow + 12);
                float xk = (kk == 0) ? xv.x : (kk == 1) ? xv.y
                         : (kk == 2) ? xv.z : xv.w;
                unsigned long long a = pack2(xk);
                ffma2(acc[0], a, w01.x); ffma2(acc[1], a, w01.y);
                ffma2(acc[2], a, w23.x); ffma2(acc[3], a, w23.y);
                ffma2(acc[4], a, w45.x); ffma2(acc[5], a, w45.y);
                ffma2(acc[6], a, w67.x); ffma2(acc[7], a, w67.y);
            }
        }
        __syncthreads();
    }

    // ---- dump logits to smem [128][65] ----
    float* lg = sm;
#pragma unroll
    for (int p = 0; p < 8; p++) {
        float lo, hi;
        unpack2(acc[p], lo, hi);
        lg[tokl * 65 + e0 + 2 * p]     = lo;
        lg[tokl * 65 + e0 + 2 * p + 1] = hi;
    }
    __syncthreads();

    // ---- phase 1: per-token max / top-2 / softmax denom ----
    if (t < BM) {
        const float* row = lg + t * 65;
        float b1 = -INFINITY, b2 = -INFINITY;
        int i1 = 0, i2 = 0;
#pragma unroll
        for (int e = 0; e < N_EXP; e++) {
            float v = row[e];
            if (v > b1)      { b2 = b1; i2 = i1; b1 = v; i1 = e; }
            else if (v > b2) { b2 = v;  i2 = e; }
        }
        float ssum = 0.f;
#pragma unroll
        for (int e = 0; e < N_EXP; e++) ssum += __expf(row[e] - b1);
        float inv = 1.f / ssum;
        s_max[t] = b1; s_inv[t] = inv; s_i1[t] = i1; s_i2[t] = i2;

        int gtok = tok0 + t;
        out[OFF_TKP + gtok * 2 + 0] = inv;
        out[OFF_TKP + gtok * 2 + 1] = __expf(b2 - b1) * inv;
        out[OFF_TKI + gtok * 2 + 0] = (float)i1;
        out[OFF_TKI + gtok * 2 + 1] = (float)i2;
    }
    __syncthreads();

    // ---- phase 2: coalesced probs + dispatch ----
#pragma unroll
    for (int idx = t; idx < BM * N_EXP; idx += THREADS) {
        int tok = idx >> 6;
        int e   = idx & 63;
        float p = __expf(lg[tok * 65 + e] - s_max[tok]) * s_inv[tok];
        int gtok = tok0 + tok;
        out[OFF_PROBS + (size_t)gtok * N_EXP + e] = p;
        out[OFF_DISP  + (size_t)gtok * N_EXP + e] =
            (e == s_i1[tok] || e == s_i2[tok]) ? 1.f : 0.f;
    }
}

extern "C" void kernel_launch(void* const* d_in, const int* in_sizes, int n_in,
                              void* d_out, int out_size) {
    const float* x = (const float*)d_in[0];
    const float* W = (const float*)d_in[1];
    float* out = (float*)d_out;

    static bool attr_set = false;
    if (!attr_set) {
        cudaFuncSetAttribute(moe_router_kernel,
                             cudaFuncAttributeMaxDynamicSharedMemorySize, SMEM_BYTES);
        attr_set = true;
    }
    moe_router_kernel<<<M_TOK / BM, THREADS, SMEM_BYTES>>>(x, W, out);
}

// round 14
// speedup vs baseline: 2.2696x; 1.6011x over previous
#include <cuda_runtime.h>
#include <math.h>

// MoE router, fp32 f32x2 SIMT, W-amortized (4 tokens/thread) + k-phase split.
// warp = 128 tokens x 8 experts; 16 warps = 8 expert-groups x 2 k-phases.
// BM=128, 512 threads, grid 128, fused softmax/top2 epilogue.
// x: [16384, 2048] f32, W: [2048, 64] f32
// out (f32): dispatch[16384*64], probs[16384*64], tkp[16384*2], tki[16384*2]

#define M_TOK   16384
#define K_DIM   2048
#define N_EXP   64
#define BM      128
#define BK      64
#define NT      (K_DIM / BK)          // 32
#define THREADS 512

// stage (floats): xs [128 tok][68] (64 k + 4 pad), ws [64 k][64 e]
#define XS_STRIDE    68
#define XS_FLOATS    (BM * XS_STRIDE)          // 8704
#define WS_OFF       XS_FLOATS
#define STAGE_FLOATS (XS_FLOATS + BK * N_EXP)  // 12800
#define SMEM_BYTES   (2 * STAGE_FLOATS * 4)    // 102400 B

// epilogue logits buffer: [128][66] in stage-0 area (stage 0 free at the end)
#define LG_STRIDE 66

#define OFF_DISP  0
#define OFF_PROBS (M_TOK * N_EXP)
#define OFF_TKP   (2 * M_TOK * N_EXP)
#define OFF_TKI   (2 * M_TOK * N_EXP + 2 * M_TOK)

__device__ __forceinline__ unsigned long long pack2(float v) {
    unsigned long long r;
    asm("mov.b64 %0, {%1, %1};" : "=l"(r) : "f"(v));
    return r;
}
__device__ __forceinline__ void ffma2(unsigned long long& c, unsigned long long a,
                                      unsigned long long b) {
    asm("fma.rn.f32x2 %0, %1, %2, %0;" : "+l"(c) : "l"(a), "l"(b));
}
__device__ __forceinline__ unsigned long long add2(unsigned long long a,
                                                   unsigned long long b) {
    unsigned long long r;
    asm("add.rn.f32x2 %0, %1, %2;" : "=l"(r) : "l"(a), "l"(b));
    return r;
}
__device__ __forceinline__ void cp16(unsigned dst, const void* src) {
    asm volatile("cp.async.cg.shared.global [%0], [%1], 16;\n" :: "r"(dst), "l"(src));
}
#define CP_COMMIT() asm volatile("cp.async.commit_group;\n" ::: "memory")
#define CP_WAIT0()  asm volatile("cp.async.wait_group 0;\n" ::: "memory")

__global__ __launch_bounds__(THREADS, 1)
void moe_router_kernel(const float* __restrict__ x,
                       const float* __restrict__ W,
                       float* __restrict__ out) {
    extern __shared__ float sm[];
    __shared__ float s_max[BM], s_inv[BM];
    __shared__ int   s_i1[BM], s_i2[BM];

    const int t    = threadIdx.x;
    const int wid  = t >> 5;
    const int lane = t & 31;
    const int kp   = wid >> 3;        // k-phase 0/1 (32 k each per 64-k tile)
    const int e0   = (wid & 7) * 8;   // expert group: 8 experts
    const int tok0 = blockIdx.x * BM;
    const unsigned smb = (unsigned)__cvta_generic_to_shared(sm);

    // cp.async mappings
    // x: 128 tok x 64 k = 2048 uint4; 4 per thread
    int xa_tok[4], xa_c[4];
#pragma unroll
    for (int r = 0; r < 4; r++) {
        int idx = t + r * THREADS;
        xa_tok[r] = idx >> 4;         // 0..127
        xa_c[r]   = idx & 15;         // uint4 within 64-k row
    }
    // W: 64 k x 64 e = 1024 uint4; 2 per thread
    int wa_k[2], wa_c[2];
#pragma unroll
    for (int r = 0; r < 2; r++) {
        int idx = t + r * THREADS;    // 0..1023
        wa_k[r] = idx >> 4;           // 0..63 (k row)
        wa_c[r] = idx & 15;           // uint4 within 64-e row
    }

    unsigned long long acc[4][4];     // [token c][expert pair j]
#pragma unroll
    for (int c = 0; c < 4; c++)
#pragma unroll
        for (int j = 0; j < 4; j++) acc[c][j] = 0ull;

    // ---- prologue: stage 0 ----
#pragma unroll
    for (int r = 0; r < 4; r++)
        cp16(smb + (unsigned)(xa_tok[r] * XS_STRIDE + xa_c[r] * 4) * 4,
             x + (size_t)(tok0 + xa_tok[r]) * K_DIM + xa_c[r] * 4);
#pragma unroll
    for (int r = 0; r < 2; r++)
        cp16(smb + (unsigned)(WS_OFF + wa_k[r] * N_EXP + wa_c[r] * 4) * 4,
             W + (size_t)wa_k[r] * N_EXP + wa_c[r] * 4);
    CP_COMMIT();

#pragma unroll 1
    for (int kt = 0; kt < NT; kt++) {
        const int s = kt & 1;
        CP_WAIT0();
        __syncthreads();

        // prefetch tile kt+1 into the other stage (free since iter kt-1)
        if (kt + 1 < NT) {
            const int sn = s ^ 1;
            const int kb = (kt + 1) * BK;
            const unsigned sb = smb + (unsigned)(sn * STAGE_FLOATS) * 4;
#pragma unroll
            for (int r = 0; r < 4; r++)
                cp16(sb + (unsigned)(xa_tok[r] * XS_STRIDE + xa_c[r] * 4) * 4,
                     x + (size_t)(tok0 + xa_tok[r]) * K_DIM + kb + xa_c[r] * 4);
#pragma unroll
            for (int r = 0; r < 2; r++)
                cp16(sb + (unsigned)(WS_OFF + wa_k[r] * N_EXP + wa_c[r] * 4) * 4,
                     W + (size_t)(kb + wa_k[r]) * N_EXP + wa_c[r] * 4);
            CP_COMMIT();
        }

        // ---- compute stage s: this warp's 32-k half (kp) ----
        const float* xs = sm + s * STAGE_FLOATS + kp * 32;
        const float* ws = sm + s * STAGE_FLOATS + WS_OFF + kp * 32 * N_EXP + e0;

#pragma unroll
        for (int k4 = 0; k4 < 8; k4++) {
            float4 xv[4];
#pragma unroll
            for (int c = 0; c < 4; c++)
                xv[c] = *reinterpret_cast<const float4*>(
                    xs + (lane + 32 * c) * XS_STRIDE + k4 * 4);
#pragma unroll
            for (int kk = 0; kk < 4; kk++) {
                const float* wrow = ws + (k4 * 4 + kk) * N_EXP;
                ulonglong2 wA = *reinterpret_cast<const ulonglong2*>(wrow);
                ulonglong2 wB = *reinterpret_cast<const ulonglong2*>(wrow + 4);
#pragma unroll
                for (int c = 0; c < 4; c++) {
                    float xk = (kk == 0) ? xv[c].x : (kk == 1) ? xv[c].y
                             : (kk == 2) ? xv[c].z : xv[c].w;
                    unsigned long long a = pack2(xk);
                    ffma2(acc[c][0], a, wA.x);
                    ffma2(acc[c][1], a, wA.y);
                    ffma2(acc[c][2], a, wB.x);
                    ffma2(acc[c][3], a, wB.y);
                }
            }
        }
        // no trailing sync: next iter's CP_WAIT0 + __syncthreads covers it
    }

    // ---- k-phase reduction into lg[128][66] (stage-0 area, free now) ----
    // last tile (kt=31) computed from stage 1; stage 0 is idle.
    float* lg = sm;
    if (kp == 1) {
#pragma unroll
        for (int c = 0; c < 4; c++) {
            int tok = lane + 32 * c;
#pragma unroll
            for (int j = 0; j < 4; j++)
                *reinterpret_cast<unsigned long long*>(
                    lg + tok * LG_STRIDE + e0 + 2 * j) = acc[c][j];
        }
    }
    __syncthreads();
    if (kp == 0) {
#pragma unroll
        for (int c = 0; c < 4; c++) {
            int tok = lane + 32 * c;
#pragma unroll
            for (int j = 0; j < 4; j++) {
                unsigned long long* p = reinterpret_cast<unsigned long long*>(
                    lg + tok * LG_STRIDE + e0 + 2 * j);
                *p = add2(*p, acc[c][j]);
            }
        }
    }
    __syncthreads();

    // ---- phase 1: per-token max / top-2 / softmax denom ----
    if (t < BM) {
        const float* row = lg + t * LG_STRIDE;
        float b1 = -INFINITY, b2 = -INFINITY;
        int i1 = 0, i2 = 0;
#pragma unroll
        for (int e = 0; e < N_EXP; e++) {
            float v = row[e];
            if (v > b1)      { b2 = b1; i2 = i1; b1 = v; i1 = e; }
            else if (v > b2) { b2 = v;  i2 = e; }
        }
        float ssum = 0.f;
#pragma unroll
        for (int e = 0; e < N_EXP; e++) ssum += __expf(row[e] - b1);
        float inv = 1.f / ssum;
        s_max[t] = b1; s_inv[t] = inv; s_i1[t] = i1; s_i2[t] = i2;

        int gtok = tok0 + t;
        out[OFF_TKP + gtok * 2 + 0] = inv;
        out[OFF_TKP + gtok * 2 + 1] = __expf(b2 - b1) * inv;
        out[OFF_TKI + gtok * 2 + 0] = (float)i1;
        out[OFF_TKI + gtok * 2 + 1] = (float)i2;
    }
    __syncthreads();

    // ---- phase 2: coalesced probs + dispatch ----
#pragma unroll
    for (int idx = t; idx < BM * N_EXP; idx += THREADS) {
        int tok = idx >> 6;
        int e   = idx & 63;
        float p = __expf(lg[tok * LG_STRIDE + e] - s_max[tok]) * s_inv[tok];
        int gtok = tok0 + tok;
        out[OFF_PROBS + (size_t)gtok * N_EXP + e] = p;
        out[OFF_DISP  + (size_t)gtok * N_EXP + e] =
            (e == s_i1[tok] || e == s_i2[tok]) ? 1.f : 0.f;
    }
}

extern "C" void kernel_launch(void* const* d_in, const int* in_sizes, int n_in,
                              void* d_out, int out_size) {
    const float* x = (const float*)d_in[0];
    const float* W = (const float*)d_in[1];
    float* out = (float*)d_out;

    static bool attr_set = false;
    if (!attr_set) {
        cudaFuncSetAttribute(moe_router_kernel,
                             cudaFuncAttributeMaxDynamicSharedMemorySize, SMEM_BYTES);
        attr_set = true;
    }
    moe_router_kernel<<<M_TOK / BM, THREADS, SMEM_BYTES>>>(x, W, out);
}